// round 2
// baseline (speedup 1.0000x reference)
#include <cuda_runtime.h>
#include <math.h>

// Problem constants
#define B_   32
#define H_   14
#define W_   14
#define C_   32
#define K_   64
#define KS_  5
#define OH_  10
#define P_   100          // OH*OW
#define N_   196          // H*W
#define ROWPAD 36         // smem row stride: 36*4=144B -> 16B aligned rows, 4-bank rotation

#define MU_OUT_ELEMS (B_*P_*K_)          // 204800
#define SIG_OFFSET   MU_OUT_ELEMS

// Scratch (device globals; no allocation allowed)
__device__ float g_diagvals[B_*P_*K_];   // v1 + sp*tr
__device__ float g_G[B_*P_*P_];          // Gram matrices

// ---------- f32x2 packed helpers ----------
typedef unsigned long long ull;

__device__ __forceinline__ ull f2_pack(float x, float y) {
    ull r; asm("mov.b64 %0, {%1,%2};" : "=l"(r) : "f"(x), "f"(y)); return r;
}
__device__ __forceinline__ void f2_fma(ull& d, ull a, ull b) {
    asm("fma.rn.f32x2 %0, %1, %2, %3;" : "=l"(d) : "l"(a), "l"(b), "l"(d));
}
__device__ __forceinline__ ull f2_mul(ull a, ull b) {
    ull d; asm("mul.rn.f32x2 %0, %1, %2;" : "=l"(d) : "l"(a), "l"(b)); return d;
}
__device__ __forceinline__ ull f2_add(ull a, ull b) {
    ull d; asm("add.rn.f32x2 %0, %1, %2;" : "=l"(d) : "l"(a), "l"(b)); return d;
}
__device__ __forceinline__ float2 f2_unpack(ull v) {
    float x, y; asm("mov.b64 {%0,%1}, %2;" : "=f"(x), "=f"(y) : "l"(v));
    return make_float2(x, y);
}

// =====================================================================
// Kernel 1: both conv paths + fused diag gather.
//   mu_out[b,p,k]    = sum_m A[p,m] * w[m,k]
//   diagvals[b,p,k]  = sum_m D[p,m] * w[m,k]^2 + sp[k]*sum_m D[p,m]
// grid (10 p-tiles of 10, 32 batches), blockDim 160.
// Thread org: 4 c-groups (8 ch) x (5 tp x 8 tk). Thread tile 2(p) x 8(k).
// Smem: mu_s 7056 + ds_s 7056 + w_s 2048 (1 ij chunk) + trb 80 = 64960 B
// =====================================================================
extern "C" __global__ void __launch_bounds__(160)
k1_conv(const float* __restrict__ mu_in, const float* __restrict__ Sigma,
        const float* __restrict__ w_mu, const float* __restrict__ w_sigma,
        float* __restrict__ out_base) {
    extern __shared__ float smem[];
    float* mu_s = smem;                  // 7056
    float* ds_s = smem + 7056;           // 7056
    float* w_s  = smem + 14112;          // 2048
    float* trb  = smem + 16160;          // 80

    const int b     = blockIdx.y;
    const int pbase = blockIdx.x * 10;
    const int tid   = threadIdx.x;
    const int g     = tid / 40;          // c-group 0..3
    const int w40   = tid % 40;
    const int tp    = w40 / 8;           // 0..4
    const int tk    = w40 % 8;           // 0..7
    const int kbase = tk * 8;

    // load mu_in[b] (contiguous) and the Sigma diagonal rows directly
    const float* mu_b = mu_in + b * (N_ * C_);
    for (int idx = tid; idx < N_ * C_; idx += 160) {
        int pos = idx >> 5, c = idx & 31;
        mu_s[pos * ROWPAD + c] = mu_b[idx];
    }
    for (int idx = tid; idx < N_ * 8; idx += 160) {
        int n = idx >> 3, c4 = idx & 7;
        size_t src = ((size_t)(b * N_ + n) * N_ + n) * C_ + c4 * 4;
        float4 v = *reinterpret_cast<const float4*>(Sigma + src);
        *reinterpret_cast<float4*>(&ds_s[n * ROWPAD + c4 * 4]) = v;
    }

    int prc[2];
#pragma unroll
    for (int r = 0; r < 2; ++r) {
        int p = pbase + tp * 2 + r;
        prc[r] = (p / OH_) * W_ + (p % OH_);
    }

    ull accA[2][4], accV[2][4];
#pragma unroll
    for (int r = 0; r < 2; ++r)
#pragma unroll
        for (int kk = 0; kk < 4; ++kk) { accA[r][kk] = 0ull; accV[r][kk] = 0ull; }
    float trp[2] = {0.f, 0.f};

    for (int ij = 0; ij < 25; ++ij) {
        __syncthreads();
        const float* wg = w_mu + ij * (C_ * K_);
        for (int idx = tid; idx < 512; idx += 160) {
            float4 v = *reinterpret_cast<const float4*>(wg + idx * 4);
            *reinterpret_cast<float4*>(&w_s[idx * 4]) = v;
        }
        __syncthreads();

        int ijoff = (ij / KS_) * W_ + (ij % KS_);
        int ao[2];
#pragma unroll
        for (int r = 0; r < 2; ++r) ao[r] = (prc[r] + ijoff) * ROWPAD + g * 8;

#pragma unroll
        for (int cc = 0; cc < 8; ++cc) {
            float a[2], d[2];
#pragma unroll
            for (int r = 0; r < 2; ++r) {
                a[r] = mu_s[ao[r] + cc];
                d[r] = ds_s[ao[r] + cc];
            }
            const ull* wp = reinterpret_cast<const ull*>(&w_s[(g * 8 + cc) * K_ + kbase]);
            ull wv[4], w2[4];
#pragma unroll
            for (int kk = 0; kk < 4; ++kk) { wv[kk] = wp[kk]; w2[kk] = f2_mul(wv[kk], wv[kk]); }
#pragma unroll
            for (int r = 0; r < 2; ++r) {
                ull aa = f2_pack(a[r], a[r]);
                ull dd = f2_pack(d[r], d[r]);
#pragma unroll
                for (int kk = 0; kk < 4; ++kk) {
                    f2_fma(accA[r][kk], aa, wv[kk]);
                    f2_fma(accV[r][kk], dd, w2[kk]);
                }
            }
            // same value across all tk for a given (g,tp,r); all accumulate, tk==0 writes
#pragma unroll
            for (int r = 0; r < 2; ++r) trp[r] += d[r];
        }
    }

    // cross-group reduction: reuse mu_s/ds_s region as buffer
    __syncthreads();
    ull* redu = reinterpret_cast<ull*>(smem);
    if (tk == 0) {
#pragma unroll
        for (int r = 0; r < 2; ++r) trb[g * 10 + tp * 2 + r] = trp[r];
    }
    if (g > 0) {
        ull* dst = redu + ((g - 1) * 40 + w40) * 16;
#pragma unroll
        for (int r = 0; r < 2; ++r)
#pragma unroll
            for (int kk = 0; kk < 4; ++kk) {
                dst[r * 4 + kk]     = accA[r][kk];
                dst[8 + r * 4 + kk] = accV[r][kk];
            }
    }
    __syncthreads();

    if (g == 0) {
#pragma unroll
        for (int gg = 1; gg < 4; ++gg) {
            const ull* src = redu + ((gg - 1) * 40 + w40) * 16;
#pragma unroll
            for (int r = 0; r < 2; ++r)
#pragma unroll
                for (int kk = 0; kk < 4; ++kk) {
                    accA[r][kk] = f2_add(accA[r][kk], src[r * 4 + kk]);
                    accV[r][kk] = f2_add(accV[r][kk], src[8 + r * 4 + kk]);
                }
        }
        float sp8[8];
#pragma unroll
        for (int q = 0; q < 8; ++q) sp8[q] = log1pf(expf(w_sigma[kbase + q]));

        float* mu_out = out_base;
#pragma unroll
        for (int r = 0; r < 2; ++r) {
            int lp = tp * 2 + r;
            float trt = trb[lp] + trb[10 + lp] + trb[20 + lp] + trb[30 + lp];
            int p  = pbase + lp;
            int ob = (b * P_ + p) * K_ + kbase;
#pragma unroll
            for (int kk = 0; kk < 4; ++kk) {
                float2 ma = f2_unpack(accA[r][kk]);
                *reinterpret_cast<float2*>(&mu_out[ob + kk * 2]) = ma;
                float2 mv = f2_unpack(accV[r][kk]);
                float2 dv = make_float2(mv.x + sp8[kk * 2] * trt,
                                        mv.y + sp8[kk * 2 + 1] * trt);
                *reinterpret_cast<float2*>(&g_diagvals[ob + kk * 2]) = dv;
            }
        }
    }
}

// =====================================================================
// Kernel 2: G = mu_p * mu_p^T  -> g_G scratch (no epilogue).
// grid (10 p-tiles of 10, 32 batches), blockDim 160.
// 4 c-groups x (2 tp x 20 tq), thread tile 5x5, f32x2-packed over c.
// =====================================================================
extern "C" __global__ void __launch_bounds__(160)
k2_gram(const float* __restrict__ mu_in) {
    __shared__ float mu_s[N_ * ROWPAD];   // 7056
    __shared__ float gbuf[4 * 1000];

    const int b   = blockIdx.y;
    const int p0  = blockIdx.x * 10;
    const int tid = threadIdx.x;
    const int g   = tid / 40;
    const int w40 = tid % 40;
    const int tp  = w40 / 20;   // 0..1
    const int tq  = w40 % 20;   // 0..19

    const float* mu_b = mu_in + b * (N_ * C_);
    for (int idx = tid; idx < N_ * C_; idx += 160) {
        int pos = idx >> 5, c = idx & 31;
        mu_s[pos * ROWPAD + c] = mu_b[idx];
    }
    __syncthreads();

    int prc[5], qrc[5];
#pragma unroll
    for (int r = 0; r < 5; ++r) {
        int p = p0 + tp * 5 + r;
        prc[r] = (p / OH_) * W_ + (p % OH_);
        int q = tq * 5 + r;
        qrc[r] = (q / OH_) * W_ + (q % OH_);
    }

    ull acc[25];
#pragma unroll
    for (int i = 0; i < 25; ++i) acc[i] = 0ull;

    for (int ij = 0; ij < 25; ++ij) {
        int ijoff = (ij / KS_) * W_ + (ij % KS_);
        int ao[5], bo[5];
#pragma unroll
        for (int r = 0; r < 5; ++r) {
            ao[r] = (prc[r] + ijoff) * ROWPAD + g * 8;
            bo[r] = (qrc[r] + ijoff) * ROWPAD + g * 8;
        }
#pragma unroll
        for (int c2 = 0; c2 < 4; ++c2) {
            int o2 = c2 * 2;
            ull a2[5], b2[5];
#pragma unroll
            for (int r = 0; r < 5; ++r) {
                a2[r] = *reinterpret_cast<const ull*>(&mu_s[ao[r] + o2]);
                b2[r] = *reinterpret_cast<const ull*>(&mu_s[bo[r] + o2]);
            }
#pragma unroll
            for (int r = 0; r < 5; ++r)
#pragma unroll
                for (int s = 0; s < 5; ++s)
                    f2_fma(acc[r * 5 + s], a2[r], b2[s]);
        }
    }

#pragma unroll
    for (int r = 0; r < 5; ++r)
#pragma unroll
        for (int s = 0; s < 5; ++s) {
            float2 v = f2_unpack(acc[r * 5 + s]);
            gbuf[g * 1000 + (tp * 5 + r) * 100 + tq * 5 + s] = v.x + v.y;
        }
    __syncthreads();

    for (int idx = tid; idx < 1000; idx += 160) {
        float gv = gbuf[idx] + gbuf[1000 + idx] + gbuf[2000 + idx] + gbuf[3000 + idx];
        g_G[(b * P_ + p0 + idx / 100) * P_ + (idx % 100)] = gv;
    }
}

// =====================================================================
// Kernel 3: streaming epilogue.
// Sigma_out[b,p,q,k] = sp[k]*G[b,p,q] + (p==q)*diagvals[b,p,k], abs on q==k.
// grid (100 p, 32 b), blockDim 256. One (b,p) row of 100*64 floats per block.
// =====================================================================
extern "C" __global__ void __launch_bounds__(256)
k3_epi(const float* __restrict__ w_sigma, float* __restrict__ out_base) {
    __shared__ float gs[P_];
    __shared__ float4 sp4[16];
    __shared__ float4 dv4[16];

    const int b   = blockIdx.y;
    const int p   = blockIdx.x;
    const int tid = threadIdx.x;

    if (tid < P_) gs[tid] = g_G[(b * P_ + p) * P_ + tid];
    if (tid < 64) {
        reinterpret_cast<float*>(sp4)[tid] = log1pf(expf(w_sigma[tid]));
        reinterpret_cast<float*>(dv4)[tid] = g_diagvals[(b * P_ + p) * K_ + tid];
    }
    __syncthreads();

    float* row = out_base + SIG_OFFSET + (size_t)(b * P_ + p) * (P_ * K_);
#pragma unroll 2
    for (int idx = tid; idx < 1600; idx += 256) {
        int q  = idx >> 4;
        int k4 = idx & 15;
        int kb = k4 * 4;
        float gv = gs[q];
        float4 s = sp4[k4];
        float4 o;
        o.x = s.x * gv; o.y = s.y * gv; o.z = s.z * gv; o.w = s.w * gv;
        if (q == p) {
            float4 d = dv4[k4];
            o.x += d.x; o.y += d.y; o.z += d.z; o.w += d.w;
        }
        if (q == kb)     o.x = fabsf(o.x);
        if (q == kb + 1) o.y = fabsf(o.y);
        if (q == kb + 2) o.z = fabsf(o.z);
        if (q == kb + 3) o.w = fabsf(o.w);
        *reinterpret_cast<float4*>(&row[idx * 4]) = o;
    }
}

// =====================================================================
// Launch
// =====================================================================
extern "C" void kernel_launch(void* const* d_in, const int* in_sizes, int n_in,
                              void* d_out, int out_size) {
    const float* mu_in    = (const float*)d_in[0];
    const float* Sigma_in = (const float*)d_in[1];
    const float* w_mu     = (const float*)d_in[2];
    const float* w_sigma  = (const float*)d_in[3];
    float* out = (float*)d_out;

    cudaFuncSetAttribute(k1_conv, cudaFuncAttributeMaxDynamicSharedMemorySize, 64960);

    k1_conv<<<dim3(10, 32), 160, 64960>>>(mu_in, Sigma_in, w_mu, w_sigma, out);
    k2_gram<<<dim3(10, 32), 160>>>(mu_in);
    k3_epi<<<dim3(100, 32), 256>>>(w_sigma, out);
}

// round 5
// speedup vs baseline: 1.2131x; 1.2131x over previous
#include <cuda_runtime.h>
#include <math.h>

// Problem constants
#define B_   32
#define H_   14
#define W_   14
#define C_   32
#define K_   64
#define KS_  5
#define OH_  10
#define P_   100          // OH*OW
#define N_   196          // H*W
#define NC_  6272         // N*C
#define ROWPAD 36
#define BPK  (B_*P_*K_)   // 204800

#define SIG_OFFSET BPK

// Scratch (device globals; no allocation allowed). All written before read,
// every replay, with plain stores -> deterministic.
__device__ float g_diag[B_*N_*C_];       // diag(Sigma_in): [b][n][c]
__device__ float g_sdiag[B_*N_];         // sum_c diag
__device__ float g_muP[5*BPK];           // conv(mu) partial sums, one slice per m-chunk
__device__ float g_v1P[5*BPK];           // conv(diag, w^2) partial sums per m-chunk
__device__ float g_G[B_*P_*P_];          // Gram matrices
__device__ float g_wT[51200];            // w   in [m/4][k][4] layout
__device__ float g_wsqT[51200];          // w^2 in [m/4][k][4] layout

typedef unsigned long long ull;

__device__ __forceinline__ ull f2_pack(float x, float y) {
    ull r; asm("mov.b64 %0, {%1,%2};" : "=l"(r) : "f"(x), "f"(y)); return r;
}
__device__ __forceinline__ void f2_fma(ull& d, ull a, ull b) {
    asm("fma.rn.f32x2 %0, %1, %2, %3;" : "=l"(d) : "l"(a), "l"(b), "l"(d));
}
__device__ __forceinline__ float2 f2_unpack(ull v) {
    float x, y; asm("mov.b64 {%0,%1}, %2;" : "=f"(x), "=f"(y) : "l"(v));
    return make_float2(x, y);
}

// =====================================================================
// Prepass: transpose+square weights into [m/4][k][4] layout
// =====================================================================
__global__ void k_w(const float* __restrict__ w_mu) {
    int t = blockIdx.x * 256 + threadIdx.x;     // 200 x 256 = 51200
    int m = t >> 6, k = t & 63;
    float v = w_mu[t];                          // w[m][k], flat == t
    int dst = (m >> 2) * 256 + k * 4 + (m & 3);
    g_wT[dst] = v;
    g_wsqT[dst] = v * v;
}

// =====================================================================
// Kernel 0: gather diag of Sigma_in -> g_diag, per-n channel sums -> g_sdiag
// =====================================================================
__global__ void k0_diag(const float* __restrict__ Sigma) {
    int t = blockIdx.x * blockDim.x + threadIdx.x;  // 196 x 256 = 50176
    int c4 = t & 7;
    int n  = (t >> 3) % N_;
    int b  = t / (N_ * 8);
    size_t src = ((size_t)(b * N_ + n) * N_ + n) * C_ + c4 * 4;
    float4 v = *reinterpret_cast<const float4*>(Sigma + src);
    *reinterpret_cast<float4*>(&g_diag[(b * N_ + n) * C_ + c4 * 4]) = v;
    float s = v.x + v.y + v.z + v.w;
    s += __shfl_xor_sync(0xffffffffu, s, 1);
    s += __shfl_xor_sync(0xffffffffu, s, 2);
    s += __shfl_xor_sync(0xffffffffu, s, 4);
    if (c4 == 0) g_sdiag[b * N_ + n] = s;
}

// =====================================================================
// Conv kernel (both paths): slice[mc][b,p,k] = sum_{m in chunk mc} X[p,m]*Wt[m,k]
// grid (4, 5, 32): x = pt*2+path, y = m-chunk (5 ij rows), z = b.
// block 320 = 10 warps; warp owns 5 p's (all lanes same p), lanes = k pairs.
// FFMA2 packed over m. Weights double-buffered per-ij (8 KB stages).
// Static smem: x_s 28224 + w_s 2*8192 = 44608 B (< 48 KB, no opt-in)
// Plain stores into per-chunk slices -> no atomics, deterministic.
// =====================================================================
extern "C" __global__ void __launch_bounds__(320)
k_conv(const float* __restrict__ mu_in) {
    __shared__ float x_s[N_ * ROWPAD];      // 7056 floats
    __shared__ float w_s[2][2048];          // per-ij weight stages

    const int b    = blockIdx.z;
    const int mc   = blockIdx.y;
    const int pt   = blockIdx.x >> 1;
    const int path = blockIdx.x & 1;
    const int tid  = threadIdx.x;
    const int wid  = tid >> 5;
    const int lane = tid & 31;

    const float* src = (path ? g_diag : mu_in) + b * NC_;
    for (int i = tid; i < NC_; i += 320)
        x_s[(i >> 5) * ROWPAD + (i & 31)] = src[i];

    const float4* wsrc = reinterpret_cast<const float4*>(path ? g_wsqT : g_wT)
                         + mc * 2560;       // 5 stages x 512 float4
    for (int i = tid; i < 512; i += 320)
        reinterpret_cast<float4*>(w_s[0])[i] = wsrc[i];
    __syncthreads();

    const int pbase = pt * 50 + wid * 5;
    int prc[5];
#pragma unroll
    for (int r = 0; r < 5; ++r) {
        int p = pbase + r;
        prc[r] = (p / OH_) * W_ + (p % OH_);
    }

    ull acc[5][2];
#pragma unroll
    for (int r = 0; r < 5; ++r) { acc[r][0] = 0ull; acc[r][1] = 0ull; }

#pragma unroll
    for (int ijl = 0; ijl < 5; ++ijl) {
        // prefetch next stage into the other buffer
        if (ijl < 4) {
            const float4* ws = wsrc + (ijl + 1) * 512;
            float4* wd = reinterpret_cast<float4*>(w_s[(ijl + 1) & 1]);
            for (int i = tid; i < 512; i += 320) wd[i] = ws[i];
        }

        int ij = mc * 5 + ijl;
        int ijoff = (ij / KS_) * W_ + (ij % KS_);
        int ao[5];
#pragma unroll
        for (int r = 0; r < 5; ++r) ao[r] = (prc[r] + ijoff) * ROWPAD;
        const ull* wij = reinterpret_cast<const ull*>(w_s[ijl & 1]);

#pragma unroll
        for (int c4 = 0; c4 < 8; ++c4) {
            const ull* wrow = wij + c4 * 128;
            ull w0a = wrow[lane * 2];
            ull w0b = wrow[lane * 2 + 1];
            ull w1a = wrow[64 + lane * 2];
            ull w1b = wrow[64 + lane * 2 + 1];
#pragma unroll
            for (int r = 0; r < 5; ++r) {
                float4 a = *reinterpret_cast<const float4*>(x_s + ao[r] + c4 * 4);
                ull a01 = f2_pack(a.x, a.y);
                ull a23 = f2_pack(a.z, a.w);
                f2_fma(acc[r][0], a01, w0a);
                f2_fma(acc[r][0], a23, w0b);
                f2_fma(acc[r][1], a01, w1a);
                f2_fma(acc[r][1], a23, w1b);
            }
        }
        __syncthreads();
    }

    float* outp = (path ? g_v1P : g_muP) + mc * BPK;
#pragma unroll
    for (int r = 0; r < 5; ++r) {
        int ob = (b * P_ + pbase + r) * K_;
        float2 v0 = f2_unpack(acc[r][0]);
        outp[ob + lane] = v0.x + v0.y;
        float2 v1 = f2_unpack(acc[r][1]);
        outp[ob + 32 + lane] = v1.x + v1.y;
    }
}

// =====================================================================
// Kernel 2: G = mu_p * mu_p^T  -> g_G scratch.
// =====================================================================
extern "C" __global__ void __launch_bounds__(160)
k2_gram(const float* __restrict__ mu_in) {
    __shared__ float mu_s[N_ * ROWPAD];
    __shared__ float gbuf[4 * 1000];

    const int b   = blockIdx.y;
    const int p0  = blockIdx.x * 10;
    const int tid = threadIdx.x;
    const int g   = tid / 40;
    const int w40 = tid % 40;
    const int tp  = w40 / 20;
    const int tq  = w40 % 20;

    const float* mu_b = mu_in + b * NC_;
    for (int idx = tid; idx < NC_; idx += 160) {
        int pos = idx >> 5, c = idx & 31;
        mu_s[pos * ROWPAD + c] = mu_b[idx];
    }
    __syncthreads();

    int prc[5], qrc[5];
#pragma unroll
    for (int r = 0; r < 5; ++r) {
        int p = p0 + tp * 5 + r;
        prc[r] = (p / OH_) * W_ + (p % OH_);
        int q = tq * 5 + r;
        qrc[r] = (q / OH_) * W_ + (q % OH_);
    }

    ull acc[25];
#pragma unroll
    for (int i = 0; i < 25; ++i) acc[i] = 0ull;

    for (int ij = 0; ij < 25; ++ij) {
        int ijoff = (ij / KS_) * W_ + (ij % KS_);
        int ao[5], bo[5];
#pragma unroll
        for (int r = 0; r < 5; ++r) {
            ao[r] = (prc[r] + ijoff) * ROWPAD + g * 8;
            bo[r] = (qrc[r] + ijoff) * ROWPAD + g * 8;
        }
#pragma unroll
        for (int c2 = 0; c2 < 4; ++c2) {
            int o2 = c2 * 2;
            ull a2[5], b2[5];
#pragma unroll
            for (int r = 0; r < 5; ++r) {
                a2[r] = *reinterpret_cast<const ull*>(&mu_s[ao[r] + o2]);
                b2[r] = *reinterpret_cast<const ull*>(&mu_s[bo[r] + o2]);
            }
#pragma unroll
            for (int r = 0; r < 5; ++r)
#pragma unroll
                for (int s = 0; s < 5; ++s)
                    f2_fma(acc[r * 5 + s], a2[r], b2[s]);
        }
    }

#pragma unroll
    for (int r = 0; r < 5; ++r)
#pragma unroll
        for (int s = 0; s < 5; ++s) {
            float2 v = f2_unpack(acc[r * 5 + s]);
            gbuf[g * 1000 + (tp * 5 + r) * 100 + tq * 5 + s] = v.x + v.y;
        }
    __syncthreads();

    for (int idx = tid; idx < 1000; idx += 160) {
        float gv = gbuf[idx] + gbuf[1000 + idx] + gbuf[2000 + idx] + gbuf[3000 + idx];
        g_G[(b * P_ + p0 + idx / 100) * P_ + (idx % 100)] = gv;
    }
}

// =====================================================================
// Kernel 3: streaming epilogue.
//  mu_out[b,p,k] = sum_mc g_muP[mc][b,p,k]
//  tr[b,p] = sum_{ij} sdiag[b, patch(p,ij)]
//  dv[k]   = (sum_mc g_v1P[mc][b,p,k]) + sp[k]*tr
//  Sigma_out[b,p,q,k] = sp[k]*G[b,p,q] + (q==p)*dv[k], abs on q==k
// =====================================================================
extern "C" __global__ void __launch_bounds__(256)
k3_epi(const float* __restrict__ w_sigma, float* __restrict__ out_base) {
    __shared__ float gs[P_];
    __shared__ float4 sp4[16];
    __shared__ float4 dv4[16];
    __shared__ float trs;

    const int b   = blockIdx.y;
    const int p   = blockIdx.x;
    const int tid = threadIdx.x;
    const int base = (b * P_ + p) * K_;

    float spv = 0.f, v1v = 0.f;
    if (tid < P_) gs[tid] = g_G[(b * P_ + p) * P_ + tid];
    if (tid < K_) {
        spv = log1pf(expf(w_sigma[tid]));
        reinterpret_cast<float*>(sp4)[tid] = spv;
        float muv = 0.f;
#pragma unroll
        for (int mc = 0; mc < 5; ++mc) {
            muv += g_muP[mc * BPK + base + tid];
            v1v += g_v1P[mc * BPK + base + tid];
        }
        out_base[base + tid] = muv;
    }
    if (tid < 32) {
        float v = 0.f;
        if (tid < 25) {
            int n = (p / OH_ + tid / KS_) * W_ + (p % OH_) + tid % KS_;
            v = g_sdiag[b * N_ + n];
        }
        v += __shfl_xor_sync(0xffffffffu, v, 16);
        v += __shfl_xor_sync(0xffffffffu, v, 8);
        v += __shfl_xor_sync(0xffffffffu, v, 4);
        v += __shfl_xor_sync(0xffffffffu, v, 2);
        v += __shfl_xor_sync(0xffffffffu, v, 1);
        if (tid == 0) trs = v;
    }
    __syncthreads();
    if (tid < K_) reinterpret_cast<float*>(dv4)[tid] = v1v + spv * trs;
    __syncthreads();

    float* row = out_base + SIG_OFFSET + (size_t)(b * P_ + p) * (P_ * K_);
#pragma unroll 2
    for (int idx = tid; idx < 1600; idx += 256) {
        int q  = idx >> 4;
        int k4 = idx & 15;
        int kb = k4 * 4;
        float gv = gs[q];
        float4 s = sp4[k4];
        float4 o;
        o.x = s.x * gv; o.y = s.y * gv; o.z = s.z * gv; o.w = s.w * gv;
        if (q == p) {
            float4 d = dv4[k4];
            o.x += d.x; o.y += d.y; o.z += d.z; o.w += d.w;
        }
        if (q == kb)     o.x = fabsf(o.x);
        if (q == kb + 1) o.y = fabsf(o.y);
        if (q == kb + 2) o.z = fabsf(o.z);
        if (q == kb + 3) o.w = fabsf(o.w);
        *reinterpret_cast<float4*>(&row[idx * 4]) = o;
    }
}

// =====================================================================
// Launch
// =====================================================================
extern "C" void kernel_launch(void* const* d_in, const int* in_sizes, int n_in,
                              void* d_out, int out_size) {
    const float* mu_in    = (const float*)d_in[0];
    const float* Sigma_in = (const float*)d_in[1];
    const float* w_mu     = (const float*)d_in[2];
    const float* w_sigma  = (const float*)d_in[3];
    float* out = (float*)d_out;

    k_w<<<200, 256>>>(w_mu);
    k0_diag<<<196, 256>>>(Sigma_in);
    k_conv<<<dim3(4, 5, 32), 320>>>(mu_in);
    k2_gram<<<dim3(10, 32), 160>>>(mu_in);
    k3_epi<<<dim3(100, 32), 256>>>(w_sigma, out);
}